// round 3
// baseline (speedup 1.0000x reference)
#include <cuda_runtime.h>
#include <math.h>

#define D_MODEL 768
#define D_FF    2048
#define NE      8
#define T_TOK   2048
#define CAP     2048   // per-expert row capacity (token appears in an expert at most once)

// ---------------- scratch (__device__ globals: allocation-guard safe) ----------------
__device__ int   g_count[NE];
__device__ int   g_fill[NE];
__device__ int   g_rows[NE * CAP];
__device__ float g_wts [NE * CAP];
__device__ int   g_topi[T_TOK * 2];
__device__ float g_topw[T_TOK * 2];
__device__ __align__(16) float g_h[(size_t)NE * CAP * D_FF];   // 128 MiB h-scratch

// ---------------- reset: zero output + counters ----------------
__global__ void k_reset(float* __restrict__ out, int out_n) {
    int i = blockIdx.x * blockDim.x + threadIdx.x;
    if (i < NE) { g_count[i] = 0; g_fill[i] = 0; }
    for (int j = i; j < out_n; j += gridDim.x * blockDim.x) out[j] = 0.0f;
}

// ---------------- router: one warp per token ----------------
__global__ void k_router(const float* __restrict__ x, const float* __restrict__ gw) {
    int warps_per_blk = blockDim.x >> 5;
    int t = blockIdx.x * warps_per_blk + (threadIdx.x >> 5);
    int lane = threadIdx.x & 31;
    if (t >= T_TOK) return;

    const float* xr = x + (size_t)t * D_MODEL;
    float acc[NE];
#pragma unroll
    for (int e = 0; e < NE; e++) acc[e] = 0.0f;

    for (int d = lane; d < D_MODEL; d += 32) {
        float xv = xr[d];
        const float* g = gw + (size_t)d * NE;
#pragma unroll
        for (int e = 0; e < NE; e++) acc[e] += xv * g[e];
    }
#pragma unroll
    for (int off = 16; off > 0; off >>= 1) {
#pragma unroll
        for (int e = 0; e < NE; e++) acc[e] += __shfl_xor_sync(0xFFFFFFFFu, acc[e], off);
    }

    if (lane == 0) {
        // top-1 (first occurrence on ties, matching jax top_k)
        int i0 = 0;
#pragma unroll
        for (int e = 1; e < NE; e++) if (acc[e] > acc[i0]) i0 = e;
        // top-2
        int i1 = -1; float b = -1e30f;
#pragma unroll
        for (int e = 0; e < NE; e++) if (e != i0 && acc[e] > b) { b = acc[e]; i1 = e; }

        float m  = acc[i0];
        float w0 = expf(acc[i0] - m);          // = 1
        float w1 = expf(acc[i1] - m);
        float s  = w0 + w1;
        float g0 = w0 / s, g1 = w1 / s;

        g_topi[t * 2 + 0] = i0;  g_topw[t * 2 + 0] = g0;
        g_topi[t * 2 + 1] = i1;  g_topw[t * 2 + 1] = g1;
        atomicAdd(&g_count[i0], 1);
        atomicAdd(&g_count[i1], 1);
    }
}

// ---------------- scatter: bucket (token, weight) per expert ----------------
__global__ void k_scatter() {
    int idx = blockIdx.x * blockDim.x + threadIdx.x;
    if (idx >= T_TOK * 2) return;
    int   t = idx >> 1;
    int   e = g_topi[idx];
    float w = g_topw[idx];
    int   p = atomicAdd(&g_fill[e], 1);
    g_rows[e * CAP + p] = t;
    g_wts [e * CAP + p] = w;
}

// ---------------- fused gate+up GEMM: h = silu(x@Wg) * (x@Wu), per expert ----------------
// Tile: 128 (rows) x 64 (cols) x 8 (k). 256 threads; each thread does 8x4 frags for BOTH matrices.
__global__ void __launch_bounds__(256) k_gemm_gu(
    const float* __restrict__ x,
    const float* __restrict__ wg,
    const float* __restrict__ wu)
{
    int e   = blockIdx.z;
    int cnt = g_count[e];
    int r0  = blockIdx.y * 128;
    if (r0 >= cnt) return;
    int n0  = blockIdx.x * 64;

    __shared__ float As[8][132];   // padded to dodge STS bank conflicts
    __shared__ float Bg[8][64];
    __shared__ float Bu[8][64];

    int tid = threadIdx.x;

    // A loader: thread -> (row, half-row float4)
    int la_row = tid >> 1;
    int la_k   = (tid & 1) * 4;
    int arow   = r0 + la_row;
    int tok    = (arow < cnt) ? g_rows[e * CAP + arow] : -1;
    const float* a_src = (tok >= 0) ? (x + (size_t)tok * D_MODEL) : nullptr;

    // B loader: thread -> 2 consecutive floats
    int lb   = tid * 2;
    int lb_k = lb >> 6;
    int lb_n = lb & 63;
    const float* wg_e = wg + (size_t)e * D_MODEL * D_FF;
    const float* wu_e = wu + (size_t)e * D_MODEL * D_FF;

    int tx = tid & 15;   // col group (4 cols)
    int ty = tid >> 4;   // row group (8 rows)

    float acc_g[8][4], acc_u[8][4];
#pragma unroll
    for (int i = 0; i < 8; i++)
#pragma unroll
        for (int j = 0; j < 4; j++) { acc_g[i][j] = 0.0f; acc_u[i][j] = 0.0f; }

    for (int k0 = 0; k0 < D_MODEL; k0 += 8) {
        float4 av = make_float4(0.f, 0.f, 0.f, 0.f);
        if (a_src) av = *reinterpret_cast<const float4*>(a_src + k0 + la_k);
        As[la_k + 0][la_row] = av.x;
        As[la_k + 1][la_row] = av.y;
        As[la_k + 2][la_row] = av.z;
        As[la_k + 3][la_row] = av.w;

        float2 bg = *reinterpret_cast<const float2*>(wg_e + (size_t)(k0 + lb_k) * D_FF + n0 + lb_n);
        float2 bu = *reinterpret_cast<const float2*>(wu_e + (size_t)(k0 + lb_k) * D_FF + n0 + lb_n);
        Bg[lb_k][lb_n]     = bg.x;  Bg[lb_k][lb_n + 1] = bg.y;
        Bu[lb_k][lb_n]     = bu.x;  Bu[lb_k][lb_n + 1] = bu.y;
        __syncthreads();

#pragma unroll
        for (int k = 0; k < 8; k++) {
            float a[8], bgv[4], buv[4];
#pragma unroll
            for (int i = 0; i < 8; i++) a[i] = As[k][ty * 8 + i];
#pragma unroll
            for (int j = 0; j < 4; j++) { bgv[j] = Bg[k][tx * 4 + j]; buv[j] = Bu[k][tx * 4 + j]; }
#pragma unroll
            for (int i = 0; i < 8; i++)
#pragma unroll
                for (int j = 0; j < 4; j++) {
                    acc_g[i][j] += a[i] * bgv[j];
                    acc_u[i][j] += a[i] * buv[j];
                }
        }
        __syncthreads();
    }

    // epilogue: h = silu(g) * u
#pragma unroll
    for (int i = 0; i < 8; i++) {
        int r = r0 + ty * 8 + i;
        if (r < cnt) {
            float* hrow = g_h + ((size_t)e * CAP + r) * D_FF + n0 + tx * 4;
#pragma unroll
            for (int j = 0; j < 4; j++) {
                float g = acc_g[i][j];
                float s = g / (1.0f + expf(-g));
                hrow[j] = s * acc_u[i][j];
            }
        }
    }
}

// ---------------- down GEMM: out[token] += gate * (h @ Wd), per expert ----------------
__global__ void __launch_bounds__(256) k_gemm_down(
    const float* __restrict__ wd,
    float* __restrict__ out)
{
    int e   = blockIdx.z;
    int cnt = g_count[e];
    int r0  = blockIdx.y * 128;
    if (r0 >= cnt) return;
    int n0  = blockIdx.x * 64;

    __shared__ float As[8][132];
    __shared__ float Bs[8][64];

    int tid = threadIdx.x;

    int la_row = tid >> 1;
    int la_k   = (tid & 1) * 4;
    int arow   = r0 + la_row;
    bool a_ok  = (arow < cnt);
    const float* a_src = g_h + ((size_t)e * CAP + arow) * D_FF;

    int lb   = tid * 2;
    int lb_k = lb >> 6;
    int lb_n = lb & 63;
    const float* wd_e = wd + (size_t)e * D_FF * D_MODEL;

    int tx = tid & 15;
    int ty = tid >> 4;

    float acc[8][4];
#pragma unroll
    for (int i = 0; i < 8; i++)
#pragma unroll
        for (int j = 0; j < 4; j++) acc[i][j] = 0.0f;

    for (int k0 = 0; k0 < D_FF; k0 += 8) {
        float4 av = make_float4(0.f, 0.f, 0.f, 0.f);
        if (a_ok) av = *reinterpret_cast<const float4*>(a_src + k0 + la_k);
        As[la_k + 0][la_row] = av.x;
        As[la_k + 1][la_row] = av.y;
        As[la_k + 2][la_row] = av.z;
        As[la_k + 3][la_row] = av.w;

        float2 bv = *reinterpret_cast<const float2*>(wd_e + (size_t)(k0 + lb_k) * D_MODEL + n0 + lb_n);
        Bs[lb_k][lb_n]     = bv.x;
        Bs[lb_k][lb_n + 1] = bv.y;
        __syncthreads();

#pragma unroll
        for (int k = 0; k < 8; k++) {
            float a[8], bv4[4];
#pragma unroll
            for (int i = 0; i < 8; i++) a[i] = As[k][ty * 8 + i];
#pragma unroll
            for (int j = 0; j < 4; j++) bv4[j] = Bs[k][tx * 4 + j];
#pragma unroll
            for (int i = 0; i < 8; i++)
#pragma unroll
                for (int j = 0; j < 4; j++) acc[i][j] += a[i] * bv4[j];
        }
        __syncthreads();
    }

#pragma unroll
    for (int i = 0; i < 8; i++) {
        int r = r0 + ty * 8 + i;
        if (r < cnt) {
            int   tok = g_rows[e * CAP + r];
            float w   = g_wts [e * CAP + r];
            float* orow = out + (size_t)tok * D_MODEL + n0 + tx * 4;
#pragma unroll
            for (int j = 0; j < 4; j++) atomicAdd(&orow[j], acc[i][j] * w);
        }
    }
}

// ---------------- launch ----------------
extern "C" void kernel_launch(void* const* d_in, const int* in_sizes, int n_in,
                              void* d_out, int out_size) {
    const float* x      = (const float*)d_in[0];   // [2,1024,768]
    const float* gate_w = (const float*)d_in[1];   // [768,8]
    const float* w_gate = (const float*)d_in[2];   // [8,768,2048]
    const float* w_up   = (const float*)d_in[3];   // [8,768,2048]
    const float* w_down = (const float*)d_in[4];   // [8,2048,768]
    float* out = (float*)d_out;

    // 1) reset counters + zero output (also zeroes the trailing loss scalar if present)
    k_reset<<<512, 256>>>(out, out_size);

    // 2) router: 8 warps/block -> 8 tokens/block
    k_router<<<T_TOK / 8, 256>>>(x, gate_w);

    // 3) scatter tokens into per-expert buckets
    k_scatter<<<(T_TOK * 2 + 255) / 256, 256>>>();

    // 4) fused gate/up + SiLU
    {
        dim3 grid(D_FF / 64, CAP / 128, NE);
        k_gemm_gu<<<grid, 256>>>(x, w_gate, w_up);
    }

    // 5) down projection + weighted scatter-add
    {
        dim3 grid(D_MODEL / 64, CAP / 128, NE);
        k_gemm_down<<<grid, 256>>>(w_down, out);
    }
}

// round 5
// speedup vs baseline: 2.3704x; 2.3704x over previous
#include <cuda_runtime.h>
#include <cuda_bf16.h>
#include <cstdint>
#include <math.h>

#define D_MODEL 768
#define D_FF    2048
#define NE      8
#define T_TOK   2048
#define CAP     2048

// ======================= scratch (__device__ globals) =======================
__device__ int   g_count[NE];
__device__ int   g_fill[NE];
__device__ int   g_rows[NE * CAP];
__device__ float g_wts [NE * CAP];
__device__ int   g_topi[T_TOK * 2];
__device__ float g_topw[T_TOK * 2];

__device__ __align__(16) __nv_bfloat16 g_xhi[T_TOK * D_MODEL];
__device__ __align__(16) __nv_bfloat16 g_xlo[T_TOK * D_MODEL];
// h = silu(g)*u, split hi/lo: [E][CAP][D_FF]
__device__ __align__(16) __nv_bfloat16 g_h_hi[(size_t)NE * CAP * D_FF];
__device__ __align__(16) __nv_bfloat16 g_h_lo[(size_t)NE * CAP * D_FF];

// ======================= helpers =======================
__device__ __forceinline__ uint32_t smem_u32(const void* p) {
    uint32_t a;
    asm("{ .reg .u64 t; cvta.to.shared.u64 t, %1; cvt.u32.u64 %0, t; }" : "=r"(a) : "l"(p));
    return a;
}

__device__ __forceinline__ void ldsm4(uint32_t (&r)[4], uint32_t addr) {
    asm volatile("ldmatrix.sync.aligned.m8n8.x4.shared.b16 {%0,%1,%2,%3}, [%4];"
                 : "=r"(r[0]), "=r"(r[1]), "=r"(r[2]), "=r"(r[3]) : "r"(addr));
}
__device__ __forceinline__ void ldsm4t(uint32_t (&r)[4], uint32_t addr) {
    asm volatile("ldmatrix.sync.aligned.m8n8.x4.trans.shared.b16 {%0,%1,%2,%3}, [%4];"
                 : "=r"(r[0]), "=r"(r[1]), "=r"(r[2]), "=r"(r[3]) : "r"(addr));
}
__device__ __forceinline__ void mma16816(float (&d)[4], const uint32_t (&a)[4],
                                         uint32_t b0, uint32_t b1) {
    asm volatile(
        "mma.sync.aligned.m16n8k16.row.col.f32.bf16.bf16.f32 "
        "{%0,%1,%2,%3}, {%4,%5,%6,%7}, {%8,%9}, {%0,%1,%2,%3};"
        : "+f"(d[0]), "+f"(d[1]), "+f"(d[2]), "+f"(d[3])
        : "r"(a[0]), "r"(a[1]), "r"(a[2]), "r"(a[3]), "r"(b0), "r"(b1));
}

__device__ __forceinline__ uint32_t pack2(__nv_bfloat16 a, __nv_bfloat16 b) {
    __nv_bfloat162 p = __halves2bfloat162(a, b);
    return *reinterpret_cast<uint32_t*>(&p);
}
// 8 fp32 -> 8 hi bf16 + 8 lo bf16 (packed as uint4 each)
__device__ __forceinline__ void cvt8(const float4& f0, const float4& f1,
                                     uint4& hi, uint4& lo) {
    float f[8] = {f0.x, f0.y, f0.z, f0.w, f1.x, f1.y, f1.z, f1.w};
    __nv_bfloat16 h[8], l[8];
#pragma unroll
    for (int i = 0; i < 8; i++) {
        h[i] = __float2bfloat16(f[i]);
        l[i] = __float2bfloat16(f[i] - __bfloat162float(h[i]));
    }
    hi = make_uint4(pack2(h[0], h[1]), pack2(h[2], h[3]), pack2(h[4], h[5]), pack2(h[6], h[7]));
    lo = make_uint4(pack2(l[0], l[1]), pack2(l[2], l[3]), pack2(l[4], l[5]), pack2(l[6], l[7]));
}

// ======================= small kernels =======================
__global__ void k_reset(float* __restrict__ out, int out_n) {
    int i = blockIdx.x * blockDim.x + threadIdx.x;
    if (i < NE) { g_count[i] = 0; g_fill[i] = 0; }
    for (int j = i; j < out_n; j += gridDim.x * blockDim.x) out[j] = 0.0f;
}

__global__ void k_router(const float* __restrict__ x, const float* __restrict__ gw) {
    int t = blockIdx.x * (blockDim.x >> 5) + (threadIdx.x >> 5);
    int lane = threadIdx.x & 31;
    if (t >= T_TOK) return;
    const float* xr = x + (size_t)t * D_MODEL;
    float acc[NE];
#pragma unroll
    for (int e = 0; e < NE; e++) acc[e] = 0.0f;
    for (int d = lane; d < D_MODEL; d += 32) {
        float xv = xr[d];
        const float* g = gw + (size_t)d * NE;
#pragma unroll
        for (int e = 0; e < NE; e++) acc[e] += xv * g[e];
    }
#pragma unroll
    for (int off = 16; off > 0; off >>= 1)
#pragma unroll
        for (int e = 0; e < NE; e++) acc[e] += __shfl_xor_sync(0xFFFFFFFFu, acc[e], off);

    if (lane == 0) {
        int i0 = 0;
#pragma unroll
        for (int e = 1; e < NE; e++) if (acc[e] > acc[i0]) i0 = e;
        int i1 = -1; float b = -1e30f;
#pragma unroll
        for (int e = 0; e < NE; e++) if (e != i0 && acc[e] > b) { b = acc[e]; i1 = e; }
        float w1 = expf(acc[i1] - acc[i0]);
        float s  = 1.0f + w1;
        g_topi[t * 2 + 0] = i0;  g_topw[t * 2 + 0] = 1.0f / s;
        g_topi[t * 2 + 1] = i1;  g_topw[t * 2 + 1] = w1 / s;
        atomicAdd(&g_count[i0], 1);
        atomicAdd(&g_count[i1], 1);
    }
}

__global__ void k_scatter() {
    int idx = blockIdx.x * blockDim.x + threadIdx.x;
    if (idx >= T_TOK * 2) return;
    int e = g_topi[idx];
    int p = atomicAdd(&g_fill[e], 1);
    g_rows[e * CAP + p] = idx >> 1;
    g_wts [e * CAP + p] = g_topw[idx];
}

__global__ void k_cvt_x(const float* __restrict__ x) {
    int i = blockIdx.x * blockDim.x + threadIdx.x;
    if (i >= T_TOK * D_MODEL) return;
    float v = x[i];
    __nv_bfloat16 hi = __float2bfloat16(v);
    g_xhi[i] = hi;
    g_xlo[i] = __float2bfloat16(v - __bfloat162float(hi));
}

// ======================= HMMA GEMM kernels =======================
// Tile: M=128 x N=64, K-chunk 32. 256 threads = 8 warps in 4(m) x 2(n).
// A smem row stride 40 bf16 (80B), B smem row stride 72 bf16 (144B) -> ldmatrix conflict-free.
#define SA 40
#define SB 72

// h = silu(x@Wg) * (x@Wu)  (weights read fp32 [k][n] native layout, converted inline)
__global__ void __launch_bounds__(256) k_hmma_gu(
    const float* __restrict__ wg, const float* __restrict__ wu)
{
    int e   = blockIdx.z;
    int cnt = g_count[e];
    int r0  = blockIdx.y * 128;
    if (r0 >= cnt) return;
    int n0  = blockIdx.x * 64;

    __shared__ __nv_bfloat16 sAh[128 * SA], sAl[128 * SA];
    __shared__ __nv_bfloat16 sGh[32 * SB], sGl[32 * SB];
    __shared__ __nv_bfloat16 sUh[32 * SB], sUl[32 * SB];

    int tid = threadIdx.x, lane = tid & 31, wid = tid >> 5;
    int wm = wid >> 1, wn = wid & 1;

    // --- loader setup ---
    int arow = tid >> 1, ahalf = tid & 1;
    int slotA = r0 + arow;
    int tok = (slotA < cnt) ? g_rows[e * CAP + slotA] : 0;
    const __nv_bfloat16* pAh = g_xhi + (size_t)tok * D_MODEL + ahalf * 16;
    const __nv_bfloat16* pAl = g_xlo + (size_t)tok * D_MODEL + ahalf * 16;
    __nv_bfloat16* dAh = sAh + arow * SA + ahalf * 16;
    __nv_bfloat16* dAl = sAl + arow * SA + ahalf * 16;

    int brow = tid >> 3, bq = tid & 7;      // 32 k-rows x 8 col-quads
    const float* pG = wg + (size_t)e * D_MODEL * D_FF + (size_t)brow * D_FF + n0 + bq * 8;
    const float* pU = wu + (size_t)e * D_MODEL * D_FF + (size_t)brow * D_FF + n0 + bq * 8;
    uint4* dGh = (uint4*)(sGh + brow * SB + bq * 8);
    uint4* dGl = (uint4*)(sGl + brow * SB + bq * 8);
    uint4* dUh = (uint4*)(sUh + brow * SB + bq * 8);
    uint4* dUl = (uint4*)(sUl + brow * SB + bq * 8);

    uint32_t bAh = smem_u32(sAh), bAl = smem_u32(sAl);
    uint32_t bGh = smem_u32(sGh), bGl = smem_u32(sGl);
    uint32_t bUh = smem_u32(sUh), bUl = smem_u32(sUl);

    float ag[2][4][4], au[2][4][4];
#pragma unroll
    for (int i = 0; i < 2; i++)
#pragma unroll
        for (int j = 0; j < 4; j++)
#pragma unroll
            for (int q = 0; q < 4; q++) { ag[i][j][q] = 0.0f; au[i][j][q] = 0.0f; }

    for (int c = 0; c < D_MODEL / 32; c++) {      // 24 chunks
        int k0 = c * 32;
        if (c > 0) __syncthreads();
        // A fill: 16 bf16 per thread per precision
        *(uint4*)dAh       = *(const uint4*)(pAh + k0);
        *(uint4*)(dAh + 8) = *(const uint4*)(pAh + k0 + 8);
        *(uint4*)dAl       = *(const uint4*)(pAl + k0);
        *(uint4*)(dAl + 8) = *(const uint4*)(pAl + k0 + 8);
        // B fill: 8 fp32 -> hi/lo bf16 per matrix
        {
            const float* s = pG + (size_t)k0 * D_FF;
            float4 f0 = *(const float4*)s, f1 = *(const float4*)(s + 4);
            uint4 hi, lo; cvt8(f0, f1, hi, lo);
            *dGh = hi; *dGl = lo;
        }
        {
            const float* s = pU + (size_t)k0 * D_FF;
            float4 f0 = *(const float4*)s, f1 = *(const float4*)(s + 4);
            uint4 hi, lo; cvt8(f0, f1, hi, lo);
            *dUh = hi; *dUl = lo;
        }
        __syncthreads();

#pragma unroll
        for (int kk = 0; kk < 32; kk += 16) {
            uint32_t ah[2][4], al[2][4];
#pragma unroll
            for (int mf = 0; mf < 2; mf++) {
                uint32_t ro = wm * 32 + mf * 16 + (lane & 15);
                uint32_t co = kk + (lane >> 4) * 8;
                ldsm4(ah[mf], bAh + (ro * SA + co) * 2);
                ldsm4(al[mf], bAl + (ro * SA + co) * 2);
            }
            uint32_t kr = kk + (lane & 7) + ((lane >> 4) & 1) * 8;
            uint32_t ncol = wn * 32 + ((lane >> 3) & 1) * 8;
            // ---- gate ----
            {
                uint32_t bh[4][2], bl[4][2], r4[4];
#pragma unroll
                for (int p = 0; p < 2; p++) {
                    uint32_t off = (kr * SB + ncol + p * 16) * 2;
                    ldsm4t(r4, bGh + off);
                    bh[p*2][0] = r4[0]; bh[p*2+1][0] = r4[1]; bh[p*2][1] = r4[2]; bh[p*2+1][1] = r4[3];
                    ldsm4t(r4, bGl + off);
                    bl[p*2][0] = r4[0]; bl[p*2+1][0] = r4[1]; bl[p*2][1] = r4[2]; bl[p*2+1][1] = r4[3];
                }
#pragma unroll
                for (int mf = 0; mf < 2; mf++)
#pragma unroll
                    for (int nf = 0; nf < 4; nf++) {
                        mma16816(ag[mf][nf], ah[mf], bh[nf][0], bh[nf][1]);
                        mma16816(ag[mf][nf], ah[mf], bl[nf][0], bl[nf][1]);
                        mma16816(ag[mf][nf], al[mf], bh[nf][0], bh[nf][1]);
                    }
            }
            // ---- up ----
            {
                uint32_t bh[4][2], bl[4][2], r4[4];
#pragma unroll
                for (int p = 0; p < 2; p++) {
                    uint32_t off = (kr * SB + ncol + p * 16) * 2;
                    ldsm4t(r4, bUh + off);
                    bh[p*2][0] = r4[0]; bh[p*2+1][0] = r4[1]; bh[p*2][1] = r4[2]; bh[p*2+1][1] = r4[3];
                    ldsm4t(r4, bUl + off);
                    bl[p*2][0] = r4[0]; bl[p*2+1][0] = r4[1]; bl[p*2][1] = r4[2]; bl[p*2+1][1] = r4[3];
                }
#pragma unroll
                for (int mf = 0; mf < 2; mf++)
#pragma unroll
                    for (int nf = 0; nf < 4; nf++) {
                        mma16816(au[mf][nf], ah[mf], bh[nf][0], bh[nf][1]);
                        mma16816(au[mf][nf], ah[mf], bl[nf][0], bl[nf][1]);
                        mma16816(au[mf][nf], al[mf], bh[nf][0], bh[nf][1]);
                    }
            }
        }
    }

    // ---- epilogue: h = silu(g)*u -> split bf16 ----
    int lr = lane >> 2, lc = (lane & 3) * 2;
#pragma unroll
    for (int mf = 0; mf < 2; mf++)
#pragma unroll
        for (int half = 0; half < 2; half++) {
            int slot = r0 + wm * 32 + mf * 16 + lr + half * 8;
            if (slot >= cnt) continue;
            size_t base = ((size_t)e * CAP + slot) * D_FF + n0 + wn * 32 + lc;
#pragma unroll
            for (int nf = 0; nf < 4; nf++) {
                float g0 = ag[mf][nf][half * 2 + 0], g1 = ag[mf][nf][half * 2 + 1];
                float u0 = au[mf][nf][half * 2 + 0], u1 = au[mf][nf][half * 2 + 1];
                float h0 = (g0 / (1.0f + expf(-g0))) * u0;
                float h1 = (g1 / (1.0f + expf(-g1))) * u1;
                __nv_bfloat16 h0h = __float2bfloat16(h0);
                __nv_bfloat16 h1h = __float2bfloat16(h1);
                __nv_bfloat16 h0l = __float2bfloat16(h0 - __bfloat162float(h0h));
                __nv_bfloat16 h1l = __float2bfloat16(h1 - __bfloat162float(h1h));
                *(__nv_bfloat162*)(g_h_hi + base + nf * 8) = __halves2bfloat162(h0h, h1h);
                *(__nv_bfloat162*)(g_h_lo + base + nf * 8) = __halves2bfloat162(h0l, h1l);
            }
        }
}

// out[token] += gate_wt * (h @ Wd)
__global__ void __launch_bounds__(256) k_hmma_down(
    const float* __restrict__ wd, float* __restrict__ out)
{
    int e   = blockIdx.z;
    int cnt = g_count[e];
    int r0  = blockIdx.y * 128;
    if (r0 >= cnt) return;
    int n0  = blockIdx.x * 64;

    __shared__ __nv_bfloat16 sAh[128 * SA], sAl[128 * SA];
    __shared__ __nv_bfloat16 sBh[32 * SB], sBl[32 * SB];

    int tid = threadIdx.x, lane = tid & 31, wid = tid >> 5;
    int wm = wid >> 1, wn = wid & 1;

    int arow = tid >> 1, ahalf = tid & 1;
    size_t hrow = ((size_t)e * CAP + r0 + arow) * D_FF + ahalf * 16;
    const __nv_bfloat16* pAh = g_h_hi + hrow;
    const __nv_bfloat16* pAl = g_h_lo + hrow;
    __nv_bfloat16* dAh = sAh + arow * SA + ahalf * 16;
    __nv_bfloat16* dAl = sAl + arow * SA + ahalf * 16;

    int brow = tid >> 3, bq = tid & 7;
    const float* pB = wd + (size_t)e * D_FF * D_MODEL + (size_t)brow * D_MODEL + n0 + bq * 8;
    uint4* dBh = (uint4*)(sBh + brow * SB + bq * 8);
    uint4* dBl = (uint4*)(sBl + brow * SB + bq * 8);

    uint32_t bAh = smem_u32(sAh), bAl = smem_u32(sAl);
    uint32_t bBh = smem_u32(sBh), bBl = smem_u32(sBl);

    float ac[2][4][4];
#pragma unroll
    for (int i = 0; i < 2; i++)
#pragma unroll
        for (int j = 0; j < 4; j++)
#pragma unroll
            for (int q = 0; q < 4; q++) ac[i][j][q] = 0.0f;

    for (int c = 0; c < D_FF / 32; c++) {         // 64 chunks
        int k0 = c * 32;
        if (c > 0) __syncthreads();
        *(uint4*)dAh       = *(const uint4*)(pAh + k0);
        *(uint4*)(dAh + 8) = *(const uint4*)(pAh + k0 + 8);
        *(uint4*)dAl       = *(const uint4*)(pAl + k0);
        *(uint4*)(dAl + 8) = *(const uint4*)(pAl + k0 + 8);
        {
            const float* s = pB + (size_t)k0 * D_MODEL;
            float4 f0 = *(const float4*)s, f1 = *(const float4*)(s + 4);
            uint4 hi, lo; cvt8(f0, f1, hi, lo);
            *dBh = hi; *dBl = lo;
        }
        __syncthreads();

#pragma unroll
        for (int kk = 0; kk < 32; kk += 16) {
            uint32_t ah[2][4], al[2][4];
#pragma unroll
            for (int mf = 0; mf < 2; mf++) {
                uint32_t ro = wm * 32 + mf * 16 + (lane & 15);
                uint32_t co = kk + (lane >> 4) * 8;
                ldsm4(ah[mf], bAh + (ro * SA + co) * 2);
                ldsm4(al[mf], bAl + (ro * SA + co) * 2);
            }
            uint32_t kr = kk + (lane & 7) + ((lane >> 4) & 1) * 8;
            uint32_t ncol = wn * 32 + ((lane >> 3) & 1) * 8;
            uint32_t bh[4][2], bl[4][2], r4[4];
#pragma unroll
            for (int p = 0; p < 2; p++) {
                uint32_t off = (kr * SB + ncol + p * 16) * 2;
                ldsm4t(r4, bBh + off);
                bh[p*2][0] = r4[0]; bh[p*2+1][0] = r4[1]; bh[p*2][1] = r4[2]; bh[p*2+1][1] = r4[3];
                ldsm4t(r4, bBl + off);
                bl[p*2][0] = r4[0]; bl[p*2+1][0] = r4[1]; bl[p*2][1] = r4[2]; bl[p*2+1][1] = r4[3];
            }
#pragma unroll
            for (int mf = 0; mf < 2; mf++)
#pragma unroll
                for (int nf = 0; nf < 4; nf++) {
                    mma16816(ac[mf][nf], ah[mf], bh[nf][0], bh[nf][1]);
                    mma16816(ac[mf][nf], ah[mf], bl[nf][0], bl[nf][1]);
                    mma16816(ac[mf][nf], al[mf], bh[nf][0], bh[nf][1]);
                }
        }
    }

    // ---- epilogue: weighted atomic scatter-add ----
    int lr = lane >> 2, lc = (lane & 3) * 2;
#pragma unroll
    for (int mf = 0; mf < 2; mf++)
#pragma unroll
        for (int half = 0; half < 2; half++) {
            int slot = r0 + wm * 32 + mf * 16 + lr + half * 8;
            if (slot >= cnt) continue;
            int   tok = g_rows[e * CAP + slot];
            float w   = g_wts [e * CAP + slot];
            float* orow = out + (size_t)tok * D_MODEL + n0 + wn * 32 + lc;
#pragma unroll
            for (int nf = 0; nf < 4; nf++) {
                atomicAdd(&orow[nf * 8 + 0], ac[mf][nf][half * 2 + 0] * w);
                atomicAdd(&orow[nf * 8 + 1], ac[mf][nf][half * 2 + 1] * w);
            }
        }
}

// ======================= launch =======================
extern "C" void kernel_launch(void* const* d_in, const int* in_sizes, int n_in,
                              void* d_out, int out_size) {
    const float* x      = (const float*)d_in[0];   // [2,1024,768]
    const float* gate_w = (const float*)d_in[1];   // [768,8]
    const float* w_gate = (const float*)d_in[2];   // [8,768,2048]
    const float* w_up   = (const float*)d_in[3];   // [8,768,2048]
    const float* w_down = (const float*)d_in[4];   // [8,2048,768]
    float* out = (float*)d_out;

    k_reset<<<512, 256>>>(out, out_size);
    k_router<<<T_TOK / 8, 256>>>(x, gate_w);
    k_scatter<<<(T_TOK * 2 + 255) / 256, 256>>>();
    k_cvt_x<<<(T_TOK * D_MODEL + 255) / 256, 256>>>(x);

    {   // fused gate/up HMMA + SiLU
        dim3 grid(D_FF / 64, CAP / 128, NE);
        k_hmma_gu<<<grid, 256>>>(w_gate, w_up);
    }
    {   // down HMMA + weighted scatter-add
        dim3 grid(D_MODEL / 64, CAP / 128, NE);
        k_hmma_down<<<grid, 256>>>(w_down, out);
    }
}